// round 1
// baseline (speedup 1.0000x reference)
#include <cuda_runtime.h>

#define VOCAB 128000
#define VOCAB4 (VOCAB / 4)
#define NT 1024
#define CAP 10240
#define SUBCAP 512
#define NEGV (-1000000000.0f)
#define FULLMASK 0xffffffffu

__global__ __launch_bounds__(NT, 2)
void topk_topp_kernel(const float* __restrict__ in, float* __restrict__ out) {
    __shared__ float buf[CAP];        // 40 KB candidate values
    __shared__ int   hist[1024];      // 4 KB
    __shared__ float warp2nd[32];
    __shared__ float warpmax[32];
    __shared__ float topbuf[SUBCAP];  // 2 KB
    __shared__ float topsorted[50];
    __shared__ int   s_cnt, s_scnt, s_b1;
    __shared__ float s_t0, s_M, s_thresh;

    const int tid  = threadIdx.x;
    const int lane = tid & 31;
    const int wid  = tid >> 5;
    const float* __restrict__ x = in  + (size_t)blockIdx.x * VOCAB;
    float* __restrict__ y       = out + (size_t)blockIdx.x * VOCAB;

    // ---------- Phase 0: init ----------
    hist[tid & 1023] = 0;
    if (tid == 0) { s_cnt = 0; s_scnt = 0; s_b1 = 0; }
    if (tid < 50) topsorted[tid] = NEGV;

    // ---------- Phase 1: sample 8192 elems, per-warp top-2 ----------
    // warp w samples 256 contiguous floats at offset w*4000 (covers whole row range)
    float sv[8];
#pragma unroll
    for (int k = 0; k < 8; k++)
        sv[k] = x[wid * 4000 + lane * 8 + k];

    float lm = sv[0];
#pragma unroll
    for (int k = 1; k < 8; k++) lm = fmaxf(lm, sv[k]);
    float wm = lm;
#pragma unroll
    for (int off = 16; off > 0; off >>= 1)
        wm = fmaxf(wm, __shfl_xor_sync(FULLMASK, wm, off));
    // invalidate exactly one instance of the warp max
    unsigned bal = __ballot_sync(FULLMASK, lm == wm);
    if (lane == (__ffs(bal) - 1)) {
        bool done = false;
#pragma unroll
        for (int k = 0; k < 8; k++)
            if (!done && sv[k] == wm) { sv[k] = -3.4e38f; done = true; }
    }
    float lm2 = sv[0];
#pragma unroll
    for (int k = 1; k < 8; k++) lm2 = fmaxf(lm2, sv[k]);
    float wm2 = lm2;
#pragma unroll
    for (int off = 16; off > 0; off >>= 1)
        wm2 = fmaxf(wm2, __shfl_xor_sync(FULLMASK, wm2, off));
    if (lane == 0) { warpmax[wid] = wm; warp2nd[wid] = wm2; }
    __syncthreads();

    if (tid == 0) {
        // t0 = min over warps of warp-2nd-max:
        //   each warp has >= 2 samples >= t0  -> >= 64 row elems >= t0
        //   -> t0 <= row's 50th largest  -> candidate set contains top-50.
        float t0 = warp2nd[0], M = warpmax[0];
        for (int w = 1; w < 32; w++) {
            t0 = fminf(t0, warp2nd[w]);
            M  = fmaxf(M,  warpmax[w]);
        }
        s_t0 = t0; s_M = M;
    }
    __syncthreads();
    const float t0 = s_t0;
    const float M  = s_M;

    // ---------- Phase 2: collect candidates (v >= t0), full row read ----------
    const float4* __restrict__ x4 = (const float4*)x;
    for (int i = tid; i < VOCAB4; i += NT) {
        float4 v = x4[i];
        if (v.x >= t0) { int p = atomicAdd(&s_cnt, 1); if (p < CAP) buf[p] = v.x; }
        if (v.y >= t0) { int p = atomicAdd(&s_cnt, 1); if (p < CAP) buf[p] = v.y; }
        if (v.z >= t0) { int p = atomicAdd(&s_cnt, 1); if (p < CAP) buf[p] = v.z; }
        if (v.w >= t0) { int p = atomicAdd(&s_cnt, 1); if (p < CAP) buf[p] = v.w; }
    }
    __syncthreads();
    int cnt = s_cnt; if (cnt > CAP) cnt = CAP;

    // ---------- Phase 3: 1024-bin linear histogram over [t0, M] ----------
    // bin() is monotone non-decreasing in v (values > M clamp to bin 1023).
    const float scale = (M > t0) ? (1023.0f / (M - t0)) : 0.0f;
    for (int i = tid; i < cnt; i += NT) {
        int b = (int)((buf[i] - t0) * scale);
        b = b < 0 ? 0 : (b > 1023 ? 1023 : b);
        atomicAdd(&hist[b], 1);
    }
    __syncthreads();

    // ---------- Phase 4: B1 = largest bin with suffix count >= 50 (warp 0) ----------
    if (wid == 0) {
        int c = 0;
        for (int j = 0; j < 32; j++) c += hist[lane * 32 + j];
        int s = c;  // suffix-scan over 32 chunk sums
#pragma unroll
        for (int off = 1; off < 32; off <<= 1) {
            int t = __shfl_down_sync(FULLMASK, s, off);
            if (lane + off < 32) s += t;
        }
        unsigned bb = __ballot_sync(FULLMASK, (s >= 50) && (s - c < 50));
        if (bb) {
            int L = __ffs(bb) - 1;
            if (lane == L) {
                int acc = s - c;
                int B1 = L * 32;
                for (int j = 31; j >= 0; j--) {
                    acc += hist[L * 32 + j];
                    if (acc >= 50) { B1 = L * 32 + j; break; }
                }
                s_b1 = B1;
            }
        }
    }
    __syncthreads();
    const int B1 = s_b1;

    // ---------- Phase 5: sub-candidates (bin >= B1): suffix-count in [50, ~60] ----------
    for (int i = tid; i < cnt; i += NT) {
        float v = buf[i];
        int b = (int)((v - t0) * scale);
        b = b < 0 ? 0 : (b > 1023 ? 1023 : b);
        if (b >= B1) { int p = atomicAdd(&s_scnt, 1); if (p < SUBCAP) topbuf[p] = v; }
    }
    __syncthreads();
    int sn = s_scnt; if (sn > SUBCAP) sn = SUBCAP;

    // ---------- Phase 6: rank-sort, keep top 50 descending ----------
    for (int i = tid; i < sn; i += NT) {
        float vi = topbuf[i];
        int r = 0;
        for (int j = 0; j < sn; j++) {
            float vj = topbuf[j];
            r += (vj > vi) || (vj == vi && j < i);
        }
        if (r < 50) topsorted[r] = vi;
    }
    __syncthreads();

    // ---------- Phase 7: softmax over top-50 + nucleus cutoff ----------
    if (tid == 0) {
        float mx = topsorted[0];
        float S = 0.0f;
        for (int i = 0; i < 50; i++) S += expf(topsorted[i] - mx);
        float inv = 1.0f / S;
        // keep rank i iff i==0 or cum_{i-1} <= 0.9 (reference's shifted-cumsum rule)
        float cum = inv;  // p0 = exp(0)/S
        int m = 1;
        for (int i = 1; i < 50; i++) {
            if (cum <= 0.9f) m++;
            cum += expf(topsorted[i] - mx) * inv;
        }
        s_thresh = topsorted[m - 1];
    }
    __syncthreads();

    // ---------- Phase 8: streaming filter write ----------
    const float t = s_thresh;
    float4* __restrict__ y4 = (float4*)y;
    for (int i = tid; i < VOCAB4; i += NT) {
        float4 v = x4[i];
        v.x = (v.x >= t) ? v.x : NEGV;
        v.y = (v.y >= t) ? v.y : NEGV;
        v.z = (v.z >= t) ? v.z : NEGV;
        v.w = (v.w >= t) ? v.w : NEGV;
        __stcs(&y4[i], v);   // streaming store: don't evict row reads from L2
    }
}

extern "C" void kernel_launch(void* const* d_in, const int* in_sizes, int n_in,
                              void* d_out, int out_size) {
    const float* logits = (const float*)d_in[0];
    float* out = (float*)d_out;
    const int rows = out_size / VOCAB;  // 256
    topk_topp_kernel<<<rows, NT>>>(logits, out);
}

// round 2
// speedup vs baseline: 1.1220x; 1.1220x over previous
#include <cuda_runtime.h>

#define VOCAB 128000
#define VOCAB4 (VOCAB / 4)
#define NT 1024
#define CAP 6144
#define SUBCAP 512
#define NEGV (-1000000000.0f)
#define FULLMASK 0xffffffffu

#define DYN_SMEM (CAP * 8 + 1024 * 4)   // buf + bidx + hist = 53248 bytes

__global__ __launch_bounds__(NT, 2)
void topk_topp_fused(const float* __restrict__ in, float* __restrict__ out) {
    extern __shared__ char dyn[];
    float* buf  = (float*)dyn;                  // CAP candidate values (24 KB)
    int*   bidx = (int*)(dyn + CAP * 4);        // CAP candidate indices (24 KB)
    int*   hist = (int*)(dyn + CAP * 8);        // 1024 bins (4 KB)

    __shared__ float warp2nd[32];
    __shared__ float warpmax[32];
    __shared__ float topbuf[SUBCAP];
    __shared__ float topsorted[50];
    __shared__ int   s_cnt, s_scnt, s_b1;
    __shared__ float s_t0, s_M, s_thresh;

    const int tid  = threadIdx.x;
    const int lane = tid & 31;
    const int wid  = tid >> 5;
    const float* __restrict__ x = in  + (size_t)blockIdx.x * VOCAB;
    float* __restrict__ y       = out + (size_t)blockIdx.x * VOCAB;

    // ---------- Phase 0: init ----------
    hist[tid] = 0;
    if (tid == 0) { s_cnt = 0; s_scnt = 0; s_b1 = 0; }
    if (tid < 50) topsorted[tid] = NEGV;

    // ---------- Phase 1: sample 8192 elems, per-warp top-2 ----------
    float sv[8];
#pragma unroll
    for (int k = 0; k < 8; k++)
        sv[k] = x[wid * 4000 + lane * 8 + k];

    float lm = sv[0];
#pragma unroll
    for (int k = 1; k < 8; k++) lm = fmaxf(lm, sv[k]);
    float wm = lm;
#pragma unroll
    for (int off = 16; off > 0; off >>= 1)
        wm = fmaxf(wm, __shfl_xor_sync(FULLMASK, wm, off));
    unsigned bal = __ballot_sync(FULLMASK, lm == wm);
    if (lane == (__ffs(bal) - 1)) {
        bool done = false;
#pragma unroll
        for (int k = 0; k < 8; k++)
            if (!done && sv[k] == wm) { sv[k] = -3.4e38f; done = true; }
    }
    float lm2 = sv[0];
#pragma unroll
    for (int k = 1; k < 8; k++) lm2 = fmaxf(lm2, sv[k]);
    float wm2 = lm2;
#pragma unroll
    for (int off = 16; off > 0; off >>= 1)
        wm2 = fmaxf(wm2, __shfl_xor_sync(FULLMASK, wm2, off));
    if (lane == 0) { warpmax[wid] = wm; warp2nd[wid] = wm2; }
    __syncthreads();

    if (tid == 0) {
        // t0 = 7th-smallest warp-2nd-max: the 26 warps whose 2nd-max >= t0 each
        // contribute >= 2 samples >= t0  ->  >= 52 row elements >= t0
        // ->  t0 <= row's 50th-largest  ->  candidate set contains the top-50.
        float a[32];
        float M = warpmax[0];
        for (int w = 0; w < 32; w++) { a[w] = warp2nd[w]; M = fmaxf(M, warpmax[w]); }
        for (int k = 0; k < 7; k++) {      // partial selection sort: 7 smallest
            int mi = k;
            for (int j = k + 1; j < 32; j++) if (a[j] < a[mi]) mi = j;
            float t = a[k]; a[k] = a[mi]; a[mi] = t;
        }
        s_t0 = a[6];
        s_M  = M;
    }
    __syncthreads();
    const float t0 = s_t0;
    const float M  = s_M;

    // ---------- Phase 2: single full pass — provisional write + candidate collect ----------
    // v < t0 is final (NEGV). v >= t0 is provisionally kept and recorded for fixup.
    const float4* __restrict__ x4 = (const float4*)x;
    float4* __restrict__ y4 = (float4*)y;
#pragma unroll 2
    for (int i = tid; i < VOCAB4; i += NT) {
        float4 v = x4[i];
        float4 w;
        w.x = (v.x >= t0) ? v.x : NEGV;
        w.y = (v.y >= t0) ? v.y : NEGV;
        w.z = (v.z >= t0) ? v.z : NEGV;
        w.w = (v.w >= t0) ? v.w : NEGV;
        __stcs(&y4[i], w);
        if (v.x >= t0) { int p = atomicAdd(&s_cnt, 1); if (p < CAP) { buf[p] = v.x; bidx[p] = 4 * i + 0; } }
        if (v.y >= t0) { int p = atomicAdd(&s_cnt, 1); if (p < CAP) { buf[p] = v.y; bidx[p] = 4 * i + 1; } }
        if (v.z >= t0) { int p = atomicAdd(&s_cnt, 1); if (p < CAP) { buf[p] = v.z; bidx[p] = 4 * i + 2; } }
        if (v.w >= t0) { int p = atomicAdd(&s_cnt, 1); if (p < CAP) { buf[p] = v.w; bidx[p] = 4 * i + 3; } }
    }
    __syncthreads();
    int cnt = s_cnt; if (cnt > CAP) cnt = CAP;

    // ---------- Phase 3: 1024-bin linear histogram over [t0, M] ----------
    const float scale = (M > t0) ? (1023.0f / (M - t0)) : 0.0f;
    for (int i = tid; i < cnt; i += NT) {
        int b = (int)((buf[i] - t0) * scale);
        b = b < 0 ? 0 : (b > 1023 ? 1023 : b);
        atomicAdd(&hist[b], 1);
    }
    __syncthreads();

    // ---------- Phase 4: B1 = largest bin with suffix count >= 50 (warp 0) ----------
    if (wid == 0) {
        int c = 0;
        for (int j = 0; j < 32; j++) c += hist[lane * 32 + j];
        int s = c;
#pragma unroll
        for (int off = 1; off < 32; off <<= 1) {
            int t = __shfl_down_sync(FULLMASK, s, off);
            if (lane + off < 32) s += t;
        }
        unsigned bb = __ballot_sync(FULLMASK, (s >= 50) && (s - c < 50));
        if (bb) {
            int L = __ffs(bb) - 1;
            if (lane == L) {
                int acc = s - c;
                int B1 = L * 32;
                for (int j = 31; j >= 0; j--) {
                    acc += hist[L * 32 + j];
                    if (acc >= 50) { B1 = L * 32 + j; break; }
                }
                s_b1 = B1;
            }
        }
    }
    __syncthreads();
    const int B1 = s_b1;

    // ---------- Phase 5: sub-candidates (bin >= B1) ----------
    for (int i = tid; i < cnt; i += NT) {
        float v = buf[i];
        int b = (int)((v - t0) * scale);
        b = b < 0 ? 0 : (b > 1023 ? 1023 : b);
        if (b >= B1) { int p = atomicAdd(&s_scnt, 1); if (p < SUBCAP) topbuf[p] = v; }
    }
    __syncthreads();
    int sn = s_scnt; if (sn > SUBCAP) sn = SUBCAP;

    // ---------- Phase 6: rank-sort, keep top 50 descending ----------
    for (int i = tid; i < sn; i += NT) {
        float vi = topbuf[i];
        int r = 0;
        for (int j = 0; j < sn; j++) {
            float vj = topbuf[j];
            r += (vj > vi) || (vj == vi && j < i);
        }
        if (r < 50) topsorted[r] = vi;
    }
    __syncthreads();

    // ---------- Phase 7: softmax over top-50 + nucleus cutoff ----------
    if (tid == 0) {
        float mx = topsorted[0];
        float S = 0.0f;
        for (int i = 0; i < 50; i++) S += expf(topsorted[i] - mx);
        float inv = 1.0f / S;
        float cum = inv;           // p0
        int m = 1;
        for (int i = 1; i < 50; i++) {
            if (cum <= 0.9f) m++;
            cum += expf(topsorted[i] - mx) * inv;
        }
        s_thresh = topsorted[m - 1];
    }
    __syncthreads();

    // ---------- Phase 8: scatter fixup of failed candidates ----------
    const float t = s_thresh;
    for (int i = tid; i < cnt; i += NT)
        if (buf[i] < t) y[bidx[i]] = NEGV;
}

extern "C" void kernel_launch(void* const* d_in, const int* in_sizes, int n_in,
                              void* d_out, int out_size) {
    const float* logits = (const float*)d_in[0];
    float* out = (float*)d_out;
    const int rows = out_size / VOCAB;  // 256
    cudaFuncSetAttribute(topk_topp_fused,
                         cudaFuncAttributeMaxDynamicSharedMemorySize, DYN_SMEM);
    topk_topp_fused<<<rows, NT, DYN_SMEM>>>(logits, out);
}